// round 15
// baseline (speedup 1.0000x reference)
#include <cuda_runtime.h>

// MKMMD loss, B=256, D=256, n=512, KERNEL_MUL=2, KERNEL_NUM=5, FIX_SIGMA=None.
// Two kernels; kernel boundary = grid barrier (measured cheaper than any
// in-kernel software barrier: R5/R10/R11 fusion attempts all lost).
//
// K1 (stats, NO tail): 64 blocks x 256 threads, 8 rows/block; per-column REDs
//   into padded slots + one ws2 RED per block; exit.
// K2 (loss): WARP 0 ONLY computes the bandwidth (8 L2 loads/lane covering all
//   256 column slots -> in-warp reduce -> sh_inv). Warps 1-7 never load
//   g_s1p (R14's all-warps version was 8x the L2 traffic: L1 4.1%->13.9%,
//   K2 +0.7us). One syncthreads publishes inv16, then 1 exp + 4 squarings,
//   R13-proven fenced DOUBLE atomic tail (last arriver re-reads g_acc after
//   the counter; R12's old+bsum shortcut was a measured race).
//
// Math:
//  - sum(l2_cum) over (n,n,D) = sum_f (D-f) * (2n*S2_f - 2*S1_f^2)
//  - only 4B=1024 (row,row) pairs contribute
//  - exp(-x/(bw_base*2^k)) = e4^(2^(4-k)), e4 = exp(-x/(16*bw_base))
//  - inv16 = (n*n-n)/(4*bwsum) = 65408/bwsum
//  - cross-block loss accumulation in DOUBLE (float loses ~3e-3: R4)

#define BB 256
#define DD 256

#define K1_BLOCKS 64
#define K1_THREADS 256
#define ROWS_PB 8

#define K2_BLOCKS 128
#define K2_THREADS 256
#define K2_WARPS 8

#define PAD 32                          // one 128B line per column slot

__device__ float        g_s1p[DD * PAD];
__device__ float        g_ws2f;
__device__ double       g_acc;
__device__ unsigned int g_done2;

// ---------------------------------------------------------------------------
// Kernel 1: stats only. 64 blocks x 256 threads, 8 rows each. No tail.
// ---------------------------------------------------------------------------
__global__ void __launch_bounds__(K1_THREADS, 1) stats_kernel(
    const float* __restrict__ src, const float* __restrict__ tgt) {
    const int t    = threadIdx.x;
    const int warp = t >> 5, lane = t & 31;
    const int r0   = blockIdx.x * ROWS_PB;

    float s1 = 0.f, s2 = 0.f;
#pragma unroll
    for (int k = 0; k < ROWS_PB; ++k) {
        int r = r0 + k;
        const float* row = (r < BB) ? (src + r * DD) : (tgt + (r - BB) * DD);
        float v = row[t];
        s1 += v;
        s2 = fmaf(v, v, s2);
    }
    atomicAdd(&g_s1p[t * PAD], s1);     // RED, no return needed

    float term = (float)(DD - t) * s2;
#pragma unroll
    for (int off = 16; off > 0; off >>= 1)
        term += __shfl_xor_sync(0xffffffffu, term, off);

    __shared__ float sh_red[K1_THREADS / 32];
    if (lane == 0) sh_red[warp] = term;
    __syncthreads();
    if (t == 0) {
        float bsum = 0.f;
#pragma unroll
        for (int w = 0; w < K1_THREADS / 32; ++w) bsum += sh_red[w];
        atomicAdd(&g_ws2f, bsum);       // RED
    }
    // exit; kernel boundary publishes everything to K2
}

// ---------------------------------------------------------------------------
// Kernel 2: warp-0 bandwidth + loss; two block-wide syncs total.
// ---------------------------------------------------------------------------
__global__ void __launch_bounds__(K2_THREADS, 1) loss_kernel(
    const float* __restrict__ src, const float* __restrict__ tgt,
    float* __restrict__ out) {
    const int tid  = threadIdx.x;
    const int warp = tid >> 5;
    const int lane = tid & 31;

    __shared__ float sh_red[K2_WARPS];
    __shared__ float sh_inv;

    // ---- pair setup; issue DRAM loads first ----
    const int p   = blockIdx.x * K2_WARPS + warp;   // 0..1023; grp uniform/blk
    const int grp = p >> 8;
    const int i   = p & (BB - 1);
    const int j   = (i + 1) & (BB - 1);

    const float* pa;
    const float* pb;
    float sign;
    if (grp == 0)      { pa = src + i * DD; pb = src + j * DD; sign =  1.f; }
    else if (grp == 1) { pa = tgt + i * DD; pb = tgt + j * DD; sign =  1.f; }
    else if (grp == 2) { pa = src + i * DD; pb = tgt + j * DD; sign = -1.f; }
    else               { pa = src + j * DD; pb = tgt + i * DD; sign = -1.f; }

    const float4* a4 = reinterpret_cast<const float4*>(pa) + lane * 2;
    const float4* b4 = reinterpret_cast<const float4*>(pb) + lane * 2;
    float4 a0 = a4[0], a1 = a4[1];
    float4 b0 = b4[0], b1 = b4[1];

    // ---- warp 0 only: issue L2 loads for the bandwidth reduce ----
    float sv[8];
    float ws2 = 0.f;
    if (warp == 0) {
#pragma unroll
        for (int k = 0; k < 8; ++k)
            sv[k] = g_s1p[(lane + 32 * k) * PAD];
        ws2 = g_ws2f;                   // broadcast line
    }

    // ---- squared diffs + in-lane prefix (consumes DRAM loads) ----
    float sq[8];
    {
        float d0 = a0.x - b0.x, d1 = a0.y - b0.y, d2 = a0.z - b0.z, d3 = a0.w - b0.w;
        float d4 = a1.x - b1.x, d5 = a1.y - b1.y, d6 = a1.z - b1.z, d7 = a1.w - b1.w;
        sq[0] = d0 * d0; sq[1] = d1 * d1; sq[2] = d2 * d2; sq[3] = d3 * d3;
        sq[4] = d4 * d4; sq[5] = d5 * d5; sq[6] = d6 * d6; sq[7] = d7 * d7;
    }
    float run = 0.f;
#pragma unroll
    for (int k = 0; k < 8; ++k) { run += sq[k]; sq[k] = run; }

    float pref = run;
#pragma unroll
    for (int off = 1; off < 32; off <<= 1) {
        float y = __shfl_up_sync(0xffffffffu, pref, off);
        if (lane >= off) pref += y;
    }
    const float excl = pref - run;

    // ---- warp 0: finish bandwidth, publish ----
    if (warp == 0) {
        float part = 0.f;
#pragma unroll
        for (int k = 0; k < 8; ++k) {
            int col = lane + 32 * k;
            part = fmaf((float)(DD - col) * sv[k], sv[k], part);
        }
#pragma unroll
        for (int off = 16; off > 0; off >>= 1)
            part += __shfl_xor_sync(0xffffffffu, part, off);
        if (lane == 0) {
            float bwsum = 1024.f * ws2 - 2.f * part;  // 2n*ws2 - 2*s1sq
            sh_inv = 65408.f / bwsum;                 // (n^2-n)/(4*bwsum)
        }
    }
    __syncthreads();                    // publish inv16 (sync #1)
    const float inv16 = sh_inv;

    // ---- Gaussian multi-kernel sum: 1 exp + 4 squarings ----
    float lacc = 0.f;
#pragma unroll
    for (int k = 0; k < 8; ++k) {
        float y  = (sq[k] + excl) * inv16;
        float e4 = __expf(-y);
        float s  = e4;
        float t2 = e4 * e4;  s += t2;
        t2 *= t2;            s += t2;
        t2 *= t2;            s += t2;
        t2 *= t2;            s += t2;
        lacc += s;
    }
    lacc *= sign;

#pragma unroll
    for (int off = 16; off > 0; off >>= 1)
        lacc += __shfl_xor_sync(0xffffffffu, lacc, off);

    if (lane == 0) sh_red[warp] = lacc;
    __syncthreads();                    // sh_red ready (sync #2)

    // ---- tail: payload atomic -> fence -> counter; last arriver RE-READS --
    __shared__ bool sh_final;
    if (tid == 0) {
        float bsum = 0.f;
#pragma unroll
        for (int w = 0; w < K2_WARPS; ++w) bsum += sh_red[w];
        atomicAdd(&g_acc, (double)bsum);
        __threadfence();                // own payload performed before counter
        unsigned int c = atomicAdd(&g_done2, 1u);
        sh_final = (c == (unsigned int)(K2_BLOCKS - 1));
        if (sh_final) {
            // all payloads fenced-before their counters -> visible now
            double tot = atomicAdd(&g_acc, 0.0);
            out[0] = (float)(tot * (1.0 / 65536.0));   // / (B*D)
            g_acc   = 0.0;
            g_ws2f  = 0.f;
            g_done2 = 0u;
        }
    }
    __syncthreads();

    // ---- final block: reset column sums for the next graph replay ----
    if (sh_final) {
        g_s1p[tid * PAD] = 0.f;         // all reads of g_s1p happened long ago
    }
}

extern "C" void kernel_launch(void* const* d_in, const int* in_sizes, int n_in,
                              void* d_out, int out_size) {
    const float* src = (const float*)d_in[0];
    const float* tgt = (const float*)d_in[1];
    float* out = (float*)d_out;
    (void)in_sizes; (void)n_in; (void)out_size;

    stats_kernel<<<K1_BLOCKS, K1_THREADS>>>(src, tgt);
    loss_kernel<<<K2_BLOCKS, K2_THREADS>>>(src, tgt, out);
}

// round 16
// speedup vs baseline: 1.4421x; 1.4421x over previous
#include <cuda_runtime.h>

// MKMMD loss, B=256, D=256, n=512, KERNEL_MUL=2, KERNEL_NUM=5, FIX_SIGMA=None.
// Two kernels; kernel boundary = grid barrier (measured cheaper than any
// in-kernel software barrier: R5/R10/R11 fusion attempts all lost).
// This round composes the per-kernel measured best: K1 from R13 (128 blocks,
// best total 8.70us), K2 from R15 (warp-0 bandwidth, best ncu dur 6.34us).
// End-to-end totals have shown +/-3us envelope noise (R13 gap 2.1us vs R15
// gap 8.8us at BETTER kernel durs) — this is a controlled re-measure.
//
// K1 (stats, NO tail): 128 blocks x 256 threads, 4 rows/block; per-column
//   REDs into padded slots + one ws2 RED per block; exit.
// K2 (loss): warp 0 computes the bandwidth (8 L2 loads/lane over all 256
//   column slots -> in-warp reduce -> sh_inv; all-warps version was 8x L2
//   traffic, +0.7us, R14). Two syncthreads total. 1 exp + 4 squarings.
//   R13-proven fenced DOUBLE atomic tail (last arriver re-reads g_acc after
//   the counter; R12's old+bsum shortcut was a measured race).
//
// Math:
//  - sum(l2_cum) over (n,n,D) = sum_f (D-f) * (2n*S2_f - 2*S1_f^2)
//  - only 4B=1024 (row,row) pairs contribute
//  - exp(-x/(bw_base*2^k)) = e4^(2^(4-k)), e4 = exp(-x/(16*bw_base))
//  - inv16 = (n*n-n)/(4*bwsum) = 65408/bwsum
//  - cross-block loss accumulation in DOUBLE (float loses ~3e-3: R4)

#define BB 256
#define DD 256

#define K1_BLOCKS 128
#define K1_THREADS 256
#define ROWS_PB 4

#define K2_BLOCKS 128
#define K2_THREADS 256
#define K2_WARPS 8

#define PAD 32                          // one 128B line per column slot

__device__ float        g_s1p[DD * PAD];
__device__ float        g_ws2f;
__device__ double       g_acc;
__device__ unsigned int g_done2;

// ---------------------------------------------------------------------------
// Kernel 1: stats only. 128 blocks x 256 threads, 4 rows each. No tail.
// ---------------------------------------------------------------------------
__global__ void __launch_bounds__(K1_THREADS, 1) stats_kernel(
    const float* __restrict__ src, const float* __restrict__ tgt) {
    const int t    = threadIdx.x;
    const int warp = t >> 5, lane = t & 31;
    const int r0   = blockIdx.x * ROWS_PB;

    float s1 = 0.f, s2 = 0.f;
#pragma unroll
    for (int k = 0; k < ROWS_PB; ++k) {
        int r = r0 + k;
        const float* row = (r < BB) ? (src + r * DD) : (tgt + (r - BB) * DD);
        float v = row[t];
        s1 += v;
        s2 = fmaf(v, v, s2);
    }
    atomicAdd(&g_s1p[t * PAD], s1);     // RED, no return needed

    float term = (float)(DD - t) * s2;
#pragma unroll
    for (int off = 16; off > 0; off >>= 1)
        term += __shfl_xor_sync(0xffffffffu, term, off);

    __shared__ float sh_red[K1_THREADS / 32];
    if (lane == 0) sh_red[warp] = term;
    __syncthreads();
    if (t == 0) {
        float bsum = 0.f;
#pragma unroll
        for (int w = 0; w < K1_THREADS / 32; ++w) bsum += sh_red[w];
        atomicAdd(&g_ws2f, bsum);       // RED
    }
    // exit; kernel boundary publishes everything to K2
}

// ---------------------------------------------------------------------------
// Kernel 2: warp-0 bandwidth + loss; two block-wide syncs total.
// ---------------------------------------------------------------------------
__global__ void __launch_bounds__(K2_THREADS, 1) loss_kernel(
    const float* __restrict__ src, const float* __restrict__ tgt,
    float* __restrict__ out) {
    const int tid  = threadIdx.x;
    const int warp = tid >> 5;
    const int lane = tid & 31;

    __shared__ float sh_red[K2_WARPS];
    __shared__ float sh_inv;

    // ---- pair setup; issue DRAM loads first ----
    const int p   = blockIdx.x * K2_WARPS + warp;   // 0..1023; grp uniform/blk
    const int grp = p >> 8;
    const int i   = p & (BB - 1);
    const int j   = (i + 1) & (BB - 1);

    const float* pa;
    const float* pb;
    float sign;
    if (grp == 0)      { pa = src + i * DD; pb = src + j * DD; sign =  1.f; }
    else if (grp == 1) { pa = tgt + i * DD; pb = tgt + j * DD; sign =  1.f; }
    else if (grp == 2) { pa = src + i * DD; pb = tgt + j * DD; sign = -1.f; }
    else               { pa = src + j * DD; pb = tgt + i * DD; sign = -1.f; }

    const float4* a4 = reinterpret_cast<const float4*>(pa) + lane * 2;
    const float4* b4 = reinterpret_cast<const float4*>(pb) + lane * 2;
    float4 a0 = a4[0], a1 = a4[1];
    float4 b0 = b4[0], b1 = b4[1];

    // ---- warp 0 only: issue L2 loads for the bandwidth reduce ----
    float sv[8];
    float ws2 = 0.f;
    if (warp == 0) {
#pragma unroll
        for (int k = 0; k < 8; ++k)
            sv[k] = g_s1p[(lane + 32 * k) * PAD];
        ws2 = g_ws2f;                   // broadcast line
    }

    // ---- squared diffs + in-lane prefix (consumes DRAM loads) ----
    float sq[8];
    {
        float d0 = a0.x - b0.x, d1 = a0.y - b0.y, d2 = a0.z - b0.z, d3 = a0.w - b0.w;
        float d4 = a1.x - b1.x, d5 = a1.y - b1.y, d6 = a1.z - b1.z, d7 = a1.w - b1.w;
        sq[0] = d0 * d0; sq[1] = d1 * d1; sq[2] = d2 * d2; sq[3] = d3 * d3;
        sq[4] = d4 * d4; sq[5] = d5 * d5; sq[6] = d6 * d6; sq[7] = d7 * d7;
    }
    float run = 0.f;
#pragma unroll
    for (int k = 0; k < 8; ++k) { run += sq[k]; sq[k] = run; }

    float pref = run;
#pragma unroll
    for (int off = 1; off < 32; off <<= 1) {
        float y = __shfl_up_sync(0xffffffffu, pref, off);
        if (lane >= off) pref += y;
    }
    const float excl = pref - run;

    // ---- warp 0: finish bandwidth, publish ----
    if (warp == 0) {
        float part = 0.f;
#pragma unroll
        for (int k = 0; k < 8; ++k) {
            int col = lane + 32 * k;
            part = fmaf((float)(DD - col) * sv[k], sv[k], part);
        }
#pragma unroll
        for (int off = 16; off > 0; off >>= 1)
            part += __shfl_xor_sync(0xffffffffu, part, off);
        if (lane == 0) {
            float bwsum = 1024.f * ws2 - 2.f * part;  // 2n*ws2 - 2*s1sq
            sh_inv = 65408.f / bwsum;                 // (n^2-n)/(4*bwsum)
        }
    }
    __syncthreads();                    // publish inv16 (sync #1)
    const float inv16 = sh_inv;

    // ---- Gaussian multi-kernel sum: 1 exp + 4 squarings ----
    float lacc = 0.f;
#pragma unroll
    for (int k = 0; k < 8; ++k) {
        float y  = (sq[k] + excl) * inv16;
        float e4 = __expf(-y);
        float s  = e4;
        float t2 = e4 * e4;  s += t2;
        t2 *= t2;            s += t2;
        t2 *= t2;            s += t2;
        t2 *= t2;            s += t2;
        lacc += s;
    }
    lacc *= sign;

#pragma unroll
    for (int off = 16; off > 0; off >>= 1)
        lacc += __shfl_xor_sync(0xffffffffu, lacc, off);

    if (lane == 0) sh_red[warp] = lacc;
    __syncthreads();                    // sh_red ready (sync #2)

    // ---- tail: payload atomic -> fence -> counter; last arriver RE-READS --
    __shared__ bool sh_final;
    if (tid == 0) {
        float bsum = 0.f;
#pragma unroll
        for (int w = 0; w < K2_WARPS; ++w) bsum += sh_red[w];
        atomicAdd(&g_acc, (double)bsum);
        __threadfence();                // own payload performed before counter
        unsigned int c = atomicAdd(&g_done2, 1u);
        sh_final = (c == (unsigned int)(K2_BLOCKS - 1));
        if (sh_final) {
            // all payloads fenced-before their counters -> visible now
            double tot = atomicAdd(&g_acc, 0.0);
            out[0] = (float)(tot * (1.0 / 65536.0));   // / (B*D)
            g_acc   = 0.0;
            g_ws2f  = 0.f;
            g_done2 = 0u;
        }
    }
    __syncthreads();

    // ---- final block: reset column sums for the next graph replay ----
    if (sh_final) {
        g_s1p[tid * PAD] = 0.f;         // all reads of g_s1p happened long ago
    }
}

extern "C" void kernel_launch(void* const* d_in, const int* in_sizes, int n_in,
                              void* d_out, int out_size) {
    const float* src = (const float*)d_in[0];
    const float* tgt = (const float*)d_in[1];
    float* out = (float*)d_out;
    (void)in_sizes; (void)n_in; (void)out_size;

    stats_kernel<<<K1_BLOCKS, K1_THREADS>>>(src, tgt);
    loss_kernel<<<K2_BLOCKS, K2_THREADS>>>(src, tgt, out);
}